// round 9
// baseline (speedup 1.0000x reference)
#include <cuda_runtime.h>

#define CG_TOTAL 1225
#define PAIRS 6
#define WARPS 4   // 128 threads/block
#define FULLM 0xffffffffu
#define WLCAP 360448

__constant__ int c_cgoff[9] = {0,1,10,35,44,125,350,375,600};

// Scratch (static __device__ allowed): edge -> local index; canonical pair worklists.
__device__ int g2b_scratch[524288];
__device__ int4 wl0[WLCAP], wl1[WLCAP], wl2[WLCAP];   // 00, 01, 11
__device__ int wl_cnt[4];

// Per-block descriptor for grouped passes.
struct __align__(16) BD { int kA,kB,cA,cB,w1,w2,ob,otb; };

// 11 (D1=D2=10): type1 slots (slot,l,rowoff): (0,0,0),(1,0,1),(2,1,2),(3,2,5)
__device__ const BD BD11_1[4] = {{0,0,0,0,1,1,0,0},{1,10,0,0,1,1,1,10},{10,1,0,0,1,1,10,1},{11,11,0,0,1,1,11,11}};
__device__ const BD BD11_3[4] = {{2,20,1,35,1,3,2,20},{12,23,1,35,1,3,12,21},{20,2,35,1,3,1,20,2},{23,12,35,1,3,1,21,12}};
__device__ const BD BD11_5[4] = {{5,50,10,350,1,5,5,50},{15,55,10,350,1,5,15,51},{50,5,350,10,5,1,50,5},{55,15,350,10,5,1,51,15}};
__device__ const BD BD11_9[1] = {{26,26,44,44,3,3,22,22}};
__device__ const BD BD11_15[2]= {{35,60,125,375,3,5,25,52},{60,35,375,125,5,3,52,25}};
__device__ const BD BD11_25[1]= {{75,75,600,600,5,5,55,55}};
// 01 (D1=4,D2=10): type0 slots: (0,0,0),(2,1,1)
__device__ const BD BD01_1[2] = {{0,0,0,0,1,1,0,0},{1,10,0,0,1,1,1,4}};
__device__ const BD BD01_3[3] = {{2,20,1,35,1,3,2,8},{20,2,35,1,3,1,10,1},{23,12,35,1,3,1,11,5}};
__device__ const BD BD01_5[1] = {{5,50,10,350,1,5,5,20}};
__device__ const BD BD01_9[1] = {{26,26,44,44,3,3,12,9}};
__device__ const BD BD01_15[1]= {{35,60,125,375,3,5,15,21}};
// 00 (D1=D2=4)
__device__ const BD BD00_1[1] = {{0,0,0,0,1,1,0,0}};
__device__ const BD BD00_3[2] = {{2,20,1,35,1,3,1,4},{20,2,35,1,3,1,4,1}};
__device__ const BD BD00_9[1] = {{26,26,44,44,3,3,5,5}};

struct HP {
    const float *fe, *fn;
    const int *n1a;
    const float* cg[9];
    float *out00, *out01, *out10, *out11;
    int w1, w2, w3;      // exclusive warp-range ends for lists 00, 01, 11
};

// Pass 1: g2b scatter + worklist counter reset.
__global__ void g2b_kernel(const int* __restrict__ s00, int n00,
                           const int* __restrict__ s01, int n01,
                           const int* __restrict__ s10, int n10,
                           const int* __restrict__ s11, int n11,
                           float* __restrict__ outg)
{
    if (blockIdx.x == 0 && threadIdx.x < 4) wl_cnt[threadIdx.x] = 0;
    int total = n00 + n01 + n10 + n11;
    for (int t = blockIdx.x * blockDim.x + threadIdx.x; t < total;
         t += gridDim.x * blockDim.x) {
        const int* s; int loc;
        if (t < n00)                  { s = s00; loc = t; }
        else if (t < n00 + n01)       { s = s01; loc = t - n00; }
        else if (t < n00 + n01 + n10) { s = s10; loc = t - n00 - n01; }
        else                          { s = s11; loc = t - n00 - n01 - n10; }
        int e = __ldg(s + loc);
        g2b_scratch[e] = loc;
        outg[e] = (float)loc;
    }
}

// Pass 2: build canonical pair worklists (00: p>=j; 01: all; 11: p>=j).
__global__ void compact_kernel(const int* __restrict__ s00, int n00,
                               const int* __restrict__ s01, int n01,
                               const int* __restrict__ s11, int n11,
                               const int* __restrict__ einv,
                               const int* __restrict__ n1a, const int* __restrict__ n2a,
                               const float* __restrict__ S)
{
    int total = n00 + n01 + n11;
    for (int t = blockIdx.x * blockDim.x + threadIdx.x; t < total;
         t += gridDim.x * blockDim.x) {
        int list, loc; const int* s;
        if (t < n00)            { list = 0; s = s00; loc = t; }
        else if (t < n00 + n01) { list = 1; s = s01; loc = t - n00; }
        else                    { list = 2; s = s11; loc = t - n00 - n01; }
        int e  = __ldg(s + loc);
        int ie = __ldg(einv + e);
        int p  = g2b_scratch[ie];
        bool canon = (list == 1) || (p >= loc);
        if (!canon) continue;
        int fl = 0;
        if (e == ie) {
            int a = __ldg(n1a + e), b = __ldg(n2a + e);
            if (a == b) {
                float sx = __ldg(S+3*e), sy = __ldg(S+3*e+1), sz = __ldg(S+3*e+2);
                if (sx*sx + sy*sy + sz*sz < 1e-12f) fl = (int)0x80000000;
            }
        }
        int idx = atomicAdd(&wl_cnt[list], 1);
        int4 w = make_int4(loc, p, e | fl, ie | fl);
        if (list == 0) wl0[idx] = w; else if (list == 1) wl1[idx] = w; else wl2[idx] = w;
    }
}

// One same-SZ grouped pass over the warp's nv pairs.
template<int SZ,int NB,int D1,int D2,bool STREAMB>
__device__ __forceinline__ void pass(const BD* __restrict__ bd,
    int lane, int nv, int j, int p,
    const float* __restrict__ s_cg,
    const float* __restrict__ s_feA, const float* __restrict__ s_feB,
    float* __restrict__ out, float* __restrict__ outT)
{
    constexpr int EL = D1 * D2;
    bool valid = lane < NB * SZ;
    int L  = valid ? lane : 0;
    int bi = L / SZ;
    int t  = L - bi * SZ;
    BD d = bd[bi];
    int li = (d.w2 == 3) ? t / 3 : (d.w2 == 5) ? t / 5 : t;
    if (d.w2 == 1) li = 0;          // w2==1 -> row index is t? no: W1 rows, W2=1 col
    // correct: li = t / w2, lj = t - li*w2
    li = (d.w2 == 1) ? t : (d.w2 == 3) ? t / 3 : t / 5;
    int lj = t - li * d.w2;
    int cgAo = d.cA + t * SZ;
    int cgBo = d.cB + (lj * d.w1 + li) * SZ;
    int oidx = d.ob  + li * D2 + lj;
    int oT   = d.otb + lj * D1 + li;

    float cgA[SZ];
    float cgB[STREAMB ? 1 : SZ];
    #pragma unroll
    for (int k = 0; k < SZ; k++) cgA[k] = s_cg[cgAo + k];
    if constexpr (!STREAMB) {
        #pragma unroll
        for (int k = 0; k < SZ; k++) cgB[k] = s_cg[cgBo + k];
    }
    const float* cbs = s_cg + cgBo;

    for (int pr = 0; pr < nv; pr++) {
        const float* fa = s_feA + pr * 100 + d.kA;
        const float* fb = s_feB + pr * 100 + d.kB;
        float A = 0.f, B = 0.f;
        #pragma unroll
        for (int k = 0; k < SZ; k++) {
            A += fa[k] * cgA[k];
            B += fb[k] * (STREAMB ? cbs[k] : cgB[k]);
        }
        int jp = __shfl_sync(FULLM, j, pr);
        int pp = __shfl_sync(FULLM, p, pr);
        if (valid) {
            float M = 0.5f * (A + B);
            out [(size_t)jp * EL + oidx] = M;
            outT[(size_t)pp * EL + oT ] = M;
        }
    }
}

template<int RANGE>
__device__ __forceinline__ void ham_range(int rw, const HP& P,
    const float* __restrict__ s_cg, float* __restrict__ s_fe)
{
    int warp = threadIdx.x >> 5, lane = threadIdx.x & 31;
    float* s_feA = s_fe + warp * (2 * PAIRS * 100);
    float* s_feB = s_feA + PAIRS * 100;
    int cnt  = wl_cnt[RANGE];
    int base = rw * PAIRS;
    if (base >= cnt) return;
    int nv = min(PAIRS, cnt - base);

    const int4* wl = (RANGE == 0) ? wl0 : (RANGE == 1) ? wl1 : wl2;
    int4 w = __ldg(wl + base + min(lane, nv - 1));
    int j = w.x, p = w.y, ef = w.z, ief = w.w;

    // Stage fe rows for both sides (self flag in sign bit -> add fn row).
    for (int r = 0; r < 2 * nv; r++) {
        int pr  = r >> 1;
        int raw = __shfl_sync(FULLM, (r & 1) ? ief : ef, pr);
        int edge = raw & 0x7fffffff;
        float* dst = ((r & 1) ? s_feB : s_feA) + pr * 100;
        if (lane < 25) {
            float4 v = __ldg((const float4*)(P.fe + (size_t)edge * 100) + lane);
            if (raw < 0) {
                int a = __ldg(P.n1a + edge);
                float4 x = __ldg((const float4*)(P.fn + (size_t)a * 100) + lane);
                v.x += x.x; v.y += x.y; v.z += x.z; v.w += x.w;
            }
            ((float4*)dst)[lane] = v;
        }
    }
    __syncwarp();

    if constexpr (RANGE == 0) {
        float* o = P.out00;
        pass<1,1,4,4,false>(BD00_1, lane,nv,j,p, s_cg,s_feA,s_feB, o,o);
        pass<3,2,4,4,false>(BD00_3, lane,nv,j,p, s_cg,s_feA,s_feB, o,o);
        pass<9,1,4,4,false>(BD00_9, lane,nv,j,p, s_cg,s_feA,s_feB, o,o);
    } else if constexpr (RANGE == 1) {
        pass<1 ,2,4,10,false>(BD01_1 , lane,nv,j,p, s_cg,s_feA,s_feB, P.out01,P.out10);
        pass<3 ,3,4,10,false>(BD01_3 , lane,nv,j,p, s_cg,s_feA,s_feB, P.out01,P.out10);
        pass<5 ,1,4,10,false>(BD01_5 , lane,nv,j,p, s_cg,s_feA,s_feB, P.out01,P.out10);
        pass<9 ,1,4,10,false>(BD01_9 , lane,nv,j,p, s_cg,s_feA,s_feB, P.out01,P.out10);
        pass<15,1,4,10,false>(BD01_15, lane,nv,j,p, s_cg,s_feA,s_feB, P.out01,P.out10);
    } else {
        float* o = P.out11;
        pass<1 ,4,10,10,false>(BD11_1 , lane,nv,j,p, s_cg,s_feA,s_feB, o,o);
        pass<3 ,4,10,10,false>(BD11_3 , lane,nv,j,p, s_cg,s_feA,s_feB, o,o);
        pass<5 ,4,10,10,false>(BD11_5 , lane,nv,j,p, s_cg,s_feA,s_feB, o,o);
        pass<9 ,1,10,10,false>(BD11_9 , lane,nv,j,p, s_cg,s_feA,s_feB, o,o);
        pass<15,2,10,10,false>(BD11_15, lane,nv,j,p, s_cg,s_feA,s_feB, o,o);
        pass<25,1,10,10,true >(BD11_25, lane,nv,j,p, s_cg,s_feA,s_feB, o,o);
    }
}

__global__ __launch_bounds__(128, 8) void ham_kernel(HP P) {
    __shared__ __align__(16) float s_cg[(CG_TOTAL + 3) & ~3];
    __shared__ __align__(16) float s_fe[WARPS * 2 * PAIRS * 100];
    for (int t = threadIdx.x; t < CG_TOTAL; t += blockDim.x) {
        int q = 0;
        #pragma unroll
        for (int r = 1; r < 9; r++) if (t >= c_cgoff[r]) q = r;
        s_cg[t] = __ldg(P.cg[q] + (t - c_cgoff[q]));
    }
    __syncthreads();

    int warp = threadIdx.x >> 5;
    int gw = blockIdx.x * WARPS + warp;
    if (gw < P.w1)       ham_range<0>(gw,        P, s_cg, s_fe);
    else if (gw < P.w2)  ham_range<1>(gw - P.w1, P, s_cg, s_fe);
    else if (gw < P.w3)  ham_range<2>(gw - P.w2, P, s_cg, s_fe);
}

extern "C" void kernel_launch(void* const* d_in, const int* in_sizes, int n_in,
                              void* d_out, int out_size) {
    const float* fn   = (const float*)d_in[0];
    const float* fe   = (const float*)d_in[1];
    const float* S    = (const float*)d_in[2];
    const int*   eidx = (const int*)d_in[3];
    const int*   einv = (const int*)d_in[5];
    const int* s00 = (const int*)d_in[15]; int n00 = in_sizes[15];
    const int* s01 = (const int*)d_in[16]; int n01 = in_sizes[16];
    const int* s10 = (const int*)d_in[17]; int n10 = in_sizes[17];
    const int* s11 = (const int*)d_in[18]; int n11 = in_sizes[18];

    int E = in_sizes[1] / 100;
    const int* n1a = eidx;
    const int* n2a = eidx + E;

    HP P;
    P.fe = fe; P.fn = fn; P.n1a = n1a;
    for (int i = 0; i < 9; i++) P.cg[i] = (const float*)d_in[6 + i];
    float* out = (float*)d_out;
    P.out00 = out;
    P.out01 = P.out00 + 16LL  * n00;
    P.out10 = P.out01 + 40LL  * n01;
    P.out11 = P.out10 + 40LL  * n10;
    float* outg = P.out11 + 100LL * n11;

    // Warp-range upper bounds from full list sizes (actual counts are device-side).
    int wp00 = (n00 + PAIRS - 1) / PAIRS;
    int wp01 = (n01 + PAIRS - 1) / PAIRS;
    int wp11 = (n11 + PAIRS - 1) / PAIRS;
    P.w1 = wp00; P.w2 = wp00 + wp01; P.w3 = P.w2 + wp11;

    int tot4 = n00 + n01 + n10 + n11;
    int tot3 = n00 + n01 + n11;
    if (tot4) g2b_kernel<<<(tot4 + 255) / 256, 256>>>(s00, n00, s01, n01, s10, n10, s11, n11, outg);
    if (tot3) compact_kernel<<<(tot3 + 255) / 256, 256>>>(s00, n00, s01, n01, s11, n11, einv, n1a, n2a, S);
    int blocks = (P.w3 + WARPS - 1) / WARPS;
    if (blocks) ham_kernel<<<blocks, 128>>>(P);

    (void)n_in; (void)out_size;
}

// round 10
// speedup vs baseline: 1.6449x; 1.6449x over previous
#include <cuda_runtime.h>

#define CG_TOTAL 1225
#define PAIRS 8
#define WARPS 4   // 128 threads/block, 32 candidate pairs per block
#define FULLM 0xffffffffu

__constant__ int c_cgoff[9] = {0,1,10,35,44,125,350,375,600};

__host__ __device__ constexpr int PFX(int b) {
    const int t[16] = {0,1,2,5,10,11,12,15,20,23,26,35,50,55,60,75};
    return t[b];
}
__host__ __device__ constexpr int CGO(int p) {
    const int t[9] = {0,1,10,35,44,125,350,375,600};
    return t[p];
}

__device__ int g2b_scratch[524288];

struct KP {
    const float *fe, *fn, *S;
    const int *n1a, *n2a, *einv;
    const float* cg[9];
    const int *sel00, *sel01, *sel11;
    int n00, n01, n11;
    int b1, b2, b3;
    float *out00, *out01, *out10, *out11;
};

__global__ void g2b_kernel(const int* __restrict__ s00, int n00,
                           const int* __restrict__ s01, int n01,
                           const int* __restrict__ s10, int n10,
                           const int* __restrict__ s11, int n11,
                           float* __restrict__ outg)
{
    int total = n00 + n01 + n10 + n11;
    for (int t = blockIdx.x * blockDim.x + threadIdx.x; t < total;
         t += gridDim.x * blockDim.x) {
        const int* s; int loc;
        if (t < n00)                  { s = s00; loc = t; }
        else if (t < n00 + n01)       { s = s01; loc = t - n00; }
        else if (t < n00 + n01 + n10) { s = s10; loc = t - n00 - n01; }
        else                          { s = s11; loc = t - n00 - n01 - n10; }
        int e = __ldg(s + loc);
        g2b_scratch[e] = loc;
        outg[e] = (float)loc;
    }
}

__device__ __forceinline__ void load_cg_shared(float* s_cg, const KP& P) {
    for (int t = threadIdx.x; t < CG_TOTAL; t += blockDim.x) {
        int p = 0;
        #pragma unroll
        for (int q = 1; q < 9; q++) if (t >= c_cgoff[q]) p = q;
        s_cg[t] = __ldg(P.cg[p] + (t - c_cgoff[p]));
    }
}

// R7-style broadcast-float4 block pass (used for SZ=15, 25).
template<int L1,int L2,int AM1,int AM2,int ROFF,int COFF,int D1,int D2>
__device__ __forceinline__ void blk(int lane, int nv, int j, int p,
    const float* __restrict__ s_cg,
    const float* __restrict__ s_feA, const float* __restrict__ s_feB,
    float* __restrict__ out, float* __restrict__ outT)
{
    constexpr int W1 = 2*L1+1, W2 = 2*L2+1, SZ = W1*W2;
    constexpr int offA = PFX(4*AM1+AM2), offB = PFX(4*AM2+AM1);
    constexpr int A0 = offA & ~3, B0 = offB & ~3;
    constexpr int SA = offA - A0, SB = offB - B0;
    constexpr int NA = (SA + SZ + 3) / 4, NB = (SB + SZ + 3) / 4;

    int li = lane / W2, lj = lane % W2;
    float cgA[SZ], cgB[SZ];
    if (lane < SZ) {
        const float* ca = s_cg + CGO(L1*3+L2) + lane * SZ;
        const float* cb = s_cg + CGO(L2*3+L1) + (lj*W1+li) * SZ;
        #pragma unroll
        for (int k = 0; k < SZ; k++) cgA[k] = ca[k];
        #pragma unroll
        for (int k = 0; k < SZ; k++) cgB[k] = cb[k];
    }
    #pragma unroll 2
    for (int pr = 0; pr < nv; pr++) {
        const float4* pa = (const float4*)(s_feA + pr*100 + A0);
        const float4* pb = (const float4*)(s_feB + pr*100 + B0);
        float A = 0.f, B = 0.f;
        #pragma unroll
        for (int v = 0; v < NA; v++) {
            float4 t = pa[v];
            int k0 = 4*v - SA;
            if (k0+0 >= 0 && k0+0 < SZ) A += t.x * cgA[(k0+0 >= 0 && k0+0 < SZ) ? k0+0 : 0];
            if (k0+1 >= 0 && k0+1 < SZ) A += t.y * cgA[(k0+1 >= 0 && k0+1 < SZ) ? k0+1 : 0];
            if (k0+2 >= 0 && k0+2 < SZ) A += t.z * cgA[(k0+2 >= 0 && k0+2 < SZ) ? k0+2 : 0];
            if (k0+3 >= 0 && k0+3 < SZ) A += t.w * cgA[(k0+3 >= 0 && k0+3 < SZ) ? k0+3 : 0];
        }
        #pragma unroll
        for (int v = 0; v < NB; v++) {
            float4 t = pb[v];
            int k0 = 4*v - SB;
            if (k0+0 >= 0 && k0+0 < SZ) B += t.x * cgB[(k0+0 >= 0 && k0+0 < SZ) ? k0+0 : 0];
            if (k0+1 >= 0 && k0+1 < SZ) B += t.y * cgB[(k0+1 >= 0 && k0+1 < SZ) ? k0+1 : 0];
            if (k0+2 >= 0 && k0+2 < SZ) B += t.z * cgB[(k0+2 >= 0 && k0+2 < SZ) ? k0+2 : 0];
            if (k0+3 >= 0 && k0+3 < SZ) B += t.w * cgB[(k0+3 >= 0 && k0+3 < SZ) ? k0+3 : 0];
        }
        int jp = __shfl_sync(FULLM, j, pr);
        int pp = __shfl_sync(FULLM, p, pr);
        if (lane < SZ) {
            float M = 0.5f * (A + B);
            out [(size_t)jp * (D1*D2) + (ROFF+li)*D2 + (COFF+lj)] = M;
            outT[(size_t)pp * (D1*D2) + (COFF+lj)*D1 + (ROFF+li)] = M;
        }
    }
}

// Shared warp prologue: canonical compaction + staging. Returns nv; fills j,p.
template<bool SAME>
__device__ __forceinline__ int prologue(int rel, const KP& P,
    const int* __restrict__ sel, int n,
    float* s_feA, float* s_feB, int lane, int& j, int& p)
{
    int base = rel * PAIRS;
    if (base >= n) return 0;
    int navail = min(PAIRS, n - base);

    int e = 0, ie = 0;
    bool v = false;
    j = 0; p = 0;
    if (lane < navail) {
        j  = base + lane;
        e  = __ldg(sel + j);
        ie = __ldg(P.einv + e);
        p  = g2b_scratch[ie];
        v  = SAME ? (p >= j) : true;
    }
    unsigned m = __ballot_sync(FULLM, v);
    int nv = __popc(m);
    if (nv == 0) return 0;
    int sl = (lane < nv) ? __fns(m, 0, lane + 1) : 0;
    j  = __shfl_sync(FULLM, j,  sl);
    e  = __shfl_sync(FULLM, e,  sl);
    ie = __shfl_sync(FULLM, ie, sl);
    p  = __shfl_sync(FULLM, p,  sl);

    for (int r = 0; r < 2 * nv; r++) {
        int pr = r >> 1;
        int eA = __shfl_sync(FULLM, e,  pr);
        int eB = __shfl_sync(FULLM, ie, pr);
        int edge = (r & 1) ? eB : eA;
        float* dst = ((r & 1) ? s_feB : s_feA) + pr * 100;
        int a  = __ldg(P.n1a + edge);
        int bb = __ldg(P.n2a + edge);
        bool self = false;
        if (a == bb) {
            float sx = __ldg(P.S + 3*edge), sy = __ldg(P.S + 3*edge + 1), sz = __ldg(P.S + 3*edge + 2);
            self = (sx*sx + sy*sy + sz*sz) < 1e-12f;
        }
        if (lane < 25) {
            float4 vv = __ldg((const float4*)(P.fe + (size_t)edge * 100) + lane);
            if (self) {
                float4 w = __ldg((const float4*)(P.fn + (size_t)a * 100) + lane);
                vv.x += w.x; vv.y += w.y; vv.z += w.z; vv.w += w.w;
            }
            ((float4*)dst)[lane] = vv;
        }
    }
    __syncwarp();
    return nv;
}

// ---------------- 11 list (D=10, EL=100) ----------------
__device__ __forceinline__ void ham11(int rel, const KP& P,
    const float* __restrict__ s_cg, float* s_feA, float* s_feB, int lane)
{
    int j, p;
    int nv = prologue<true>(rel, P, P.sel11, P.n11, s_feA, s_feB, lane, j, p);
    if (nv == 0) return;
    float* o = P.out11;

    // SZ=1: 4 blocks x 8 pairs = 32 lanes, one pass.
    {
        int pr = lane >> 2;
        int m = lane & 1, h = (lane >> 1) & 1;
        int koA = 10*h + m, koB = 10*m + h;   // ob = koA, otb = koB
        float cg0 = s_cg[0];
        float A = s_feA[pr*100 + koA];
        float B = s_feB[pr*100 + koB];
        int jp = __shfl_sync(FULLM, j, pr);
        int pp = __shfl_sync(FULLM, p, pr);
        if (pr < nv) {
            float M = 0.5f * cg0 * (A + B);
            o[(size_t)jp*100 + koA] = M;
            o[(size_t)pp*100 + koB] = M;
        }
    }
    // SZ=3: 4 blocks x 3 elems x 2 pairs = 24 lanes, 4 passes.
    {
        bool act = lane < 24;
        int sub = lane >= 12 ? 1 : 0;
        int r = lane - 12*sub;
        int b = r / 3, t = r - 3*b;
        int m = b & 1, h = b >> 1;
        int koA = h ? (20 + 3*m) : (2 + 10*m);
        int koB = h ? (2 + 10*m) : (20 + 3*m);
        int cA = (h ? 35 : 1) + 3*t;
        int cB = (h ? 1 : 35) + 3*t;
        int ob  = h ? (20 + m + 10*t) : (2 + 10*m + t);
        int otb = h ? (2 + 10*m + t) : (20 + m + 10*t);
        float a0=s_cg[cA], a1=s_cg[cA+1], a2=s_cg[cA+2];
        float b0=s_cg[cB], b1=s_cg[cB+1], b2=s_cg[cB+2];
        #pragma unroll
        for (int pb = 0; pb < 8; pb += 2) {
            if (pb >= nv) break;
            int pr = pb + sub;
            const float* fa = s_feA + pr*100 + koA;
            const float* fb = s_feB + pr*100 + koB;
            float A = fa[0]*a0 + fa[1]*a1 + fa[2]*a2;
            float B = fb[0]*b0 + fb[1]*b1 + fb[2]*b2;
            int jp = __shfl_sync(FULLM, j, pr);
            int pp = __shfl_sync(FULLM, p, pr);
            if (act && pr < nv) {
                float M = 0.5f*(A+B);
                o[(size_t)jp*100 + ob ] = M;
                o[(size_t)pp*100 + otb] = M;
            }
        }
    }
    // SZ=5: 4 blocks x 5 = 20 lanes, per-pair passes.
    {
        bool act = lane < 20;
        int L = act ? lane : 0;
        int b = L / 5, t = L - 5*b;
        int m = b & 1, h = b >> 1;
        int koA = h ? (50 + 5*m) : (5 + 10*m);
        int koB = h ? (5 + 10*m) : (50 + 5*m);
        int cA = (h ? 350 : 10) + 5*t;
        int cB = (h ? 10 : 350) + 5*t;
        int ob  = h ? (50 + m + 10*t) : (5 + 10*m + t);
        int otb = h ? (5 + 10*m + t) : (50 + m + 10*t);
        float a0=s_cg[cA],a1=s_cg[cA+1],a2=s_cg[cA+2],a3=s_cg[cA+3],a4=s_cg[cA+4];
        float c0=s_cg[cB],c1=s_cg[cB+1],c2=s_cg[cB+2],c3=s_cg[cB+3],c4=s_cg[cB+4];
        #pragma unroll 2
        for (int pr = 0; pr < nv; pr++) {
            const float* fa = s_feA + pr*100 + koA;
            const float* fb = s_feB + pr*100 + koB;
            float A = fa[0]*a0 + fa[1]*a1 + fa[2]*a2 + fa[3]*a3 + fa[4]*a4;
            float B = fb[0]*c0 + fb[1]*c1 + fb[2]*c2 + fb[3]*c3 + fb[4]*c4;
            int jp = __shfl_sync(FULLM, j, pr);
            int pp = __shfl_sync(FULLM, p, pr);
            if (act) {
                float M = 0.5f*(A+B);
                o[(size_t)jp*100 + ob ] = M;
                o[(size_t)pp*100 + otb] = M;
            }
        }
    }
    // SZ=9: 1 block x 9 elems x 3 pairs = 27 lanes, 3 passes.
    {
        bool act = lane < 27;
        int L = act ? lane : 0;
        int sub = L / 9;
        int t = L - 9*sub;
        int li = t / 3, lj = t - 3*li;
        int cA = 44 + 9*t;
        int cB = 44 + 9*(3*lj + li);
        int ob  = 22 + 10*li + lj;
        int otb = 22 + 10*lj + li;
        float a[9], c[9];
        #pragma unroll
        for (int k = 0; k < 9; k++) { a[k] = s_cg[cA+k]; c[k] = s_cg[cB+k]; }
        #pragma unroll
        for (int pb = 0; pb < 9; pb += 3) {
            if (pb >= nv) break;
            int pr = pb + sub;
            if (pr > 7) pr = 7;
            const float* fa = s_feA + pr*100 + 26;
            const float* fb = s_feB + pr*100 + 26;
            float A = 0.f, B = 0.f;
            #pragma unroll
            for (int k = 0; k < 9; k++) { A += fa[k]*a[k]; B += fb[k]*c[k]; }
            int jp = __shfl_sync(FULLM, j, pr);
            int pp = __shfl_sync(FULLM, p, pr);
            if (act && pb + sub < nv) {
                float M = 0.5f*(A+B);
                o[(size_t)jp*100 + ob ] = M;
                o[(size_t)pp*100 + otb] = M;
            }
        }
    }
    // SZ=15 x2 and SZ=25: R7-style.
    blk<1,2,2,3, 2,5, 10,10>(lane, nv, j, p, s_cg, s_feA, s_feB, o, o);
    blk<2,1,3,2, 5,2, 10,10>(lane, nv, j, p, s_cg, s_feA, s_feB, o, o);
    blk<2,2,3,3, 5,5, 10,10>(lane, nv, j, p, s_cg, s_feA, s_feB, o, o);
}

// ---------------- 01 list (D1=4, D2=10, EL=40) ----------------
__device__ __forceinline__ void ham01(int rel, const KP& P,
    const float* __restrict__ s_cg, float* s_feA, float* s_feB, int lane)
{
    int j, p;
    int nv = prologue<false>(rel, P, P.sel01, P.n01, s_feA, s_feB, lane, j, p);
    if (nv == 0) return;
    float* o  = P.out01;
    float* oT = P.out10;

    // SZ=1: 2 blocks x 8 pairs = 16 lanes.
    {
        int pr = lane >> 1;
        int m = lane & 1;
        int koA = m, koB = 10*m;
        float cg0 = s_cg[0];
        float A = s_feA[pr*100 + koA];
        float B = s_feB[pr*100 + koB];
        int jp = __shfl_sync(FULLM, j, pr);
        int pp = __shfl_sync(FULLM, p, pr);
        if (lane < 16 && pr < nv) {
            float M = 0.5f * cg0 * (A + B);
            o [(size_t)jp*40 + m  ] = M;
            oT[(size_t)pp*40 + 4*m] = M;
        }
    }
    // SZ=3: 3 blocks x 3 = 9 elems, 3 pairs/pass, 3 passes.
    {
        bool act = lane < 27;
        int L = act ? lane : 0;
        int sub = L / 9;
        int r = L - 9*sub;
        int b = r / 3, t = r - 3*b;
        bool b0 = (b == 0);
        int koA = b0 ? 2  : (b == 1 ? 20 : 23);
        int koB = b0 ? 20 : (b == 1 ? 2  : 12);
        int cA = (b0 ? 1 : 35) + 3*t;
        int cB = (b0 ? 35 : 1) + 3*t;
        int ob  = b0 ? (2 + t)   : (10 + 10*t + (b - 1));
        int otb = b0 ? (8 + 4*t) : ((b - 1)*4 + 1 + t);
        float a0=s_cg[cA],a1=s_cg[cA+1],a2=s_cg[cA+2];
        float c0=s_cg[cB],c1=s_cg[cB+1],c2=s_cg[cB+2];
        #pragma unroll
        for (int pb = 0; pb < 9; pb += 3) {
            if (pb >= nv) break;
            int pr = pb + sub;
            if (pr > 7) pr = 7;
            const float* fa = s_feA + pr*100 + koA;
            const float* fb = s_feB + pr*100 + koB;
            float A = fa[0]*a0 + fa[1]*a1 + fa[2]*a2;
            float B = fb[0]*c0 + fb[1]*c1 + fb[2]*c2;
            int jp = __shfl_sync(FULLM, j, pr);
            int pp = __shfl_sync(FULLM, p, pr);
            if (act && pb + sub < nv) {
                float M = 0.5f*(A+B);
                o [(size_t)jp*40 + ob ] = M;
                oT[(size_t)pp*40 + otb] = M;
            }
        }
    }
    // SZ=5: 1 block x 5 elems, 6 pairs/pass: passes at pr=sub and pr=6+sub.
    {
        int L = lane < 30 ? lane : 0;
        int sub = L / 5;
        int t = L - 5*sub;
        int cA = 10 + 5*t, cB = 350 + 5*t;
        int ob = 5 + t, otb = 20 + 4*t;
        float a0=s_cg[cA],a1=s_cg[cA+1],a2=s_cg[cA+2],a3=s_cg[cA+3],a4=s_cg[cA+4];
        float c0=s_cg[cB],c1=s_cg[cB+1],c2=s_cg[cB+2],c3=s_cg[cB+3],c4=s_cg[cB+4];
        #pragma unroll
        for (int pb = 0; pb < 12; pb += 6) {
            if (pb >= nv) break;
            int pr = pb + sub;
            if (pr > 7) pr = 7;
            const float* fa = s_feA + pr*100 + 5;
            const float* fb = s_feB + pr*100 + 50;
            float A = fa[0]*a0 + fa[1]*a1 + fa[2]*a2 + fa[3]*a3 + fa[4]*a4;
            float B = fb[0]*c0 + fb[1]*c1 + fb[2]*c2 + fb[3]*c3 + fb[4]*c4;
            int jp = __shfl_sync(FULLM, j, pr);
            int pp = __shfl_sync(FULLM, p, pr);
            if (lane < 30 && pb + sub < nv) {
                float M = 0.5f*(A+B);
                o [(size_t)jp*40 + ob ] = M;
                oT[(size_t)pp*40 + otb] = M;
            }
        }
    }
    // SZ=9: 1 block x 9 elems, 3 pairs/pass, 3 passes.
    {
        bool act = lane < 27;
        int L = act ? lane : 0;
        int sub = L / 9;
        int t = L - 9*sub;
        int li = t / 3, lj = t - 3*li;
        int cA = 44 + 9*t;
        int cB = 44 + 9*(3*lj + li);
        int ob  = 12 + 10*li + lj;
        int otb = 9 + 4*lj + li;
        float a[9], c[9];
        #pragma unroll
        for (int k = 0; k < 9; k++) { a[k] = s_cg[cA+k]; c[k] = s_cg[cB+k]; }
        #pragma unroll
        for (int pb = 0; pb < 9; pb += 3) {
            if (pb >= nv) break;
            int pr = pb + sub;
            if (pr > 7) pr = 7;
            const float* fa = s_feA + pr*100 + 26;
            const float* fb = s_feB + pr*100 + 26;
            float A = 0.f, B = 0.f;
            #pragma unroll
            for (int k = 0; k < 9; k++) { A += fa[k]*a[k]; B += fb[k]*c[k]; }
            int jp = __shfl_sync(FULLM, j, pr);
            int pp = __shfl_sync(FULLM, p, pr);
            if (act && pb + sub < nv) {
                float M = 0.5f*(A+B);
                o [(size_t)jp*40 + ob ] = M;
                oT[(size_t)pp*40 + otb] = M;
            }
        }
    }
    // SZ=15: R7-style.
    blk<1,2,2,3, 1,5, 4,10>(lane, nv, j, p, s_cg, s_feA, s_feB, o, oT);
}

// ---------------- 00 list (D=4, EL=16) ----------------
__device__ __forceinline__ void ham00(int rel, const KP& P,
    const float* __restrict__ s_cg, float* s_feA, float* s_feB, int lane)
{
    int j, p;
    int nv = prologue<true>(rel, P, P.sel00, P.n00, s_feA, s_feB, lane, j, p);
    if (nv == 0) return;
    float* o = P.out00;

    // SZ=1: 1 block x 8 pairs = 8 lanes.
    {
        int pr = lane;
        float cg0 = s_cg[0];
        float A = s_feA[(lane < 8 ? pr : 0)*100];
        float B = s_feB[(lane < 8 ? pr : 0)*100];
        if (lane < 8 && pr < nv) {
            float M = 0.5f * cg0 * (A + B);
            o[(size_t)j*16] = M;   // lane==pr: j is this lane's own
            o[(size_t)p*16] = M;
        }
    }
    // SZ=3: 2 blocks x 3 = 6 elems, 4 pairs/pass, 2 passes.
    {
        bool act = lane < 24;
        int L = act ? lane : 0;
        int sub = L / 6;
        int r = L - 6*sub;
        int h = r >= 3 ? 1 : 0;
        int t = r - 3*h;
        int koA = h ? 20 : 2;
        int koB = h ? 2 : 20;
        int cA = (h ? 35 : 1) + 3*t;
        int cB = (h ? 1 : 35) + 3*t;
        int ob  = h ? (4 + 4*t) : (1 + t);
        int otb = h ? (1 + t)   : (4 + 4*t);
        float a0=s_cg[cA],a1=s_cg[cA+1],a2=s_cg[cA+2];
        float c0=s_cg[cB],c1=s_cg[cB+1],c2=s_cg[cB+2];
        #pragma unroll
        for (int pb = 0; pb < 8; pb += 4) {
            if (pb >= nv) break;
            int pr = pb + sub;
            const float* fa = s_feA + pr*100 + koA;
            const float* fb = s_feB + pr*100 + koB;
            float A = fa[0]*a0 + fa[1]*a1 + fa[2]*a2;
            float B = fb[0]*c0 + fb[1]*c1 + fb[2]*c2;
            int jp = __shfl_sync(FULLM, j, pr);
            int pp = __shfl_sync(FULLM, p, pr);
            if (act && pr < nv) {
                float M = 0.5f*(A+B);
                o[(size_t)jp*16 + ob ] = M;
                o[(size_t)pp*16 + otb] = M;
            }
        }
    }
    // SZ=9: 1 block, 3 pairs/pass, 3 passes.
    {
        bool act = lane < 27;
        int L = act ? lane : 0;
        int sub = L / 9;
        int t = L - 9*sub;
        int li = t / 3, lj = t - 3*li;
        int cA = 44 + 9*t;
        int cB = 44 + 9*(3*lj + li);
        int ob  = 5 + 4*li + lj;
        int otb = 5 + 4*lj + li;
        float a[9], c[9];
        #pragma unroll
        for (int k = 0; k < 9; k++) { a[k] = s_cg[cA+k]; c[k] = s_cg[cB+k]; }
        #pragma unroll
        for (int pb = 0; pb < 9; pb += 3) {
            if (pb >= nv) break;
            int pr = pb + sub;
            if (pr > 7) pr = 7;
            const float* fa = s_feA + pr*100 + 26;
            const float* fb = s_feB + pr*100 + 26;
            float A = 0.f, B = 0.f;
            #pragma unroll
            for (int k = 0; k < 9; k++) { A += fa[k]*a[k]; B += fb[k]*c[k]; }
            int jp = __shfl_sync(FULLM, j, pr);
            int pp = __shfl_sync(FULLM, p, pr);
            if (act && pb + sub < nv) {
                float M = 0.5f*(A+B);
                o[(size_t)jp*16 + ob ] = M;
                o[(size_t)pp*16 + otb] = M;
            }
        }
    }
}

__global__ __launch_bounds__(128) void fused_kernel(KP P) {
    __shared__ __align__(16) float s_cg[(CG_TOTAL + 3) & ~3];
    __shared__ __align__(16) float s_fe[WARPS * 2 * PAIRS * 100];
    load_cg_shared(s_cg, P);
    __syncthreads();

    int warp = threadIdx.x >> 5, lane = threadIdx.x & 31;
    float* s_feA = s_fe + warp * (2 * PAIRS * 100);
    float* s_feB = s_feA + PAIRS * 100;
    int b = blockIdx.x;
    int gw = b * WARPS + warp;

    if (gw < P.b1)       ham00(gw,        P, s_cg, s_feA, s_feB, lane);
    else if (gw < P.b2)  ham01(gw - P.b1, P, s_cg, s_feA, s_feB, lane);
    else if (gw < P.b3)  ham11(gw - P.b2, P, s_cg, s_feA, s_feB, lane);
}

extern "C" void kernel_launch(void* const* d_in, const int* in_sizes, int n_in,
                              void* d_out, int out_size) {
    KP P;
    P.fn   = (const float*)d_in[0];
    P.fe   = (const float*)d_in[1];
    P.S    = (const float*)d_in[2];
    const int* eidx = (const int*)d_in[3];
    P.einv = (const int*)d_in[5];
    for (int i = 0; i < 9; i++) P.cg[i] = (const float*)d_in[6 + i];
    P.sel00 = (const int*)d_in[15]; P.n00 = in_sizes[15];
    P.sel01 = (const int*)d_in[16]; P.n01 = in_sizes[16];
    const int* sel10 = (const int*)d_in[17]; int n10 = in_sizes[17];
    P.sel11 = (const int*)d_in[18]; P.n11 = in_sizes[18];

    int E = in_sizes[1] / 100;
    P.n1a = eidx;
    P.n2a = eidx + E;

    float* out = (float*)d_out;
    P.out00 = out;
    P.out01 = P.out00 + 16LL  * P.n00;
    P.out10 = P.out01 + 40LL  * P.n01;
    P.out11 = P.out10 + 40LL  * n10;
    float* outg = P.out11 + 100LL * P.n11;

    // Warp ranges (one warp per PAIRS candidates).
    int w00 = (P.n00 + PAIRS - 1) / PAIRS;
    int w01 = (P.n01 + PAIRS - 1) / PAIRS;
    int w11 = (P.n11 + PAIRS - 1) / PAIRS;
    P.b1 = w00; P.b2 = P.b1 + w01; P.b3 = P.b2 + w11;

    int tot = P.n00 + P.n01 + n10 + P.n11;
    if (tot) g2b_kernel<<<(tot + 255) / 256, 256>>>(P.sel00, P.n00, P.sel01, P.n01,
                                                    sel10, n10, P.sel11, P.n11, outg);
    int blocks = (P.b3 + WARPS - 1) / WARPS;
    if (blocks) fused_kernel<<<blocks, 128>>>(P);

    (void)n_in; (void)out_size;
}

// round 11
// speedup vs baseline: 1.7023x; 1.0349x over previous
#include <cuda_runtime.h>

#define CG_TOTAL 1225
#define PAIRS 7
#define WARPS 4   // 128 threads/block, 28 candidate pairs per block
#define FULLM 0xffffffffu

__constant__ int c_cgoff[9] = {0,1,10,35,44,125,350,375,600};

__host__ __device__ constexpr int PFX(int b) {
    const int t[16] = {0,1,2,5,10,11,12,15,20,23,26,35,50,55,60,75};
    return t[b];
}
__host__ __device__ constexpr int CGO(int p) {
    const int t[9] = {0,1,10,35,44,125,350,375,600};
    return t[p];
}

__device__ int g2b_scratch[524288];

struct KP {
    const float *fe, *fn, *S;
    const int *n1a, *n2a, *einv;
    const float* cg[9];
    const int *sel00, *sel01, *sel11;
    int n00, n01, n11;
    int b1, b2, b3;
    float *out00, *out01, *out10, *out11;
};

__global__ void g2b_kernel(const int* __restrict__ s00, int n00,
                           const int* __restrict__ s01, int n01,
                           const int* __restrict__ s10, int n10,
                           const int* __restrict__ s11, int n11,
                           float* __restrict__ outg)
{
    int total = n00 + n01 + n10 + n11;
    for (int t = blockIdx.x * blockDim.x + threadIdx.x; t < total;
         t += gridDim.x * blockDim.x) {
        const int* s; int loc;
        if (t < n00)                  { s = s00; loc = t; }
        else if (t < n00 + n01)       { s = s01; loc = t - n00; }
        else if (t < n00 + n01 + n10) { s = s10; loc = t - n00 - n01; }
        else                          { s = s11; loc = t - n00 - n01 - n10; }
        int e = __ldg(s + loc);
        g2b_scratch[e] = loc;
        outg[e] = (float)loc;
    }
}

__device__ __forceinline__ void load_cg_shared(float* s_cg, const KP& P) {
    for (int t = threadIdx.x; t < CG_TOTAL; t += blockDim.x) {
        int p = 0;
        #pragma unroll
        for (int q = 1; q < 9; q++) if (t >= c_cgoff[q]) p = q;
        s_cg[t] = __ldg(P.cg[p] + (t - c_cgoff[p]));
    }
}

// Broadcast-float4 block pass (SZ=15 regs-cgB; SZ=25 streams cgB from smem).
template<int L1,int L2,int AM1,int AM2,int ROFF,int COFF,int D1,int D2,bool STREAMB>
__device__ __forceinline__ void blk(int lane, int nv, int j, int p,
    const float* __restrict__ s_cg,
    const float* __restrict__ s_feA, const float* __restrict__ s_feB,
    float* __restrict__ out, float* __restrict__ outT)
{
    constexpr int W1 = 2*L1+1, W2 = 2*L2+1, SZ = W1*W2;
    constexpr int offA = PFX(4*AM1+AM2), offB = PFX(4*AM2+AM1);
    constexpr int A0 = offA & ~3, B0 = offB & ~3;
    constexpr int SA = offA - A0, SB = offB - B0;
    constexpr int NA = (SA + SZ + 3) / 4, NB = (SB + SZ + 3) / 4;

    int li = lane / W2, lj = lane % W2;
    const float* cbs = s_cg + CGO(L2*3+L1) + (lj*W1+li) * SZ;
    float cgA[SZ];
    float cgB[STREAMB ? 1 : SZ];
    if (lane < SZ) {
        const float* ca = s_cg + CGO(L1*3+L2) + lane * SZ;
        #pragma unroll
        for (int k = 0; k < SZ; k++) cgA[k] = ca[k];
        if constexpr (!STREAMB) {
            #pragma unroll
            for (int k = 0; k < SZ; k++) cgB[k] = cbs[k];
        }
    }
    #pragma unroll 2
    for (int pr = 0; pr < nv; pr++) {
        const float4* pa = (const float4*)(s_feA + pr*100 + A0);
        const float4* pb = (const float4*)(s_feB + pr*100 + B0);
        float A = 0.f, B = 0.f;
        #pragma unroll
        for (int v = 0; v < NA; v++) {
            float4 t = pa[v];
            int k0 = 4*v - SA;
            if (k0+0 >= 0 && k0+0 < SZ) A += t.x * cgA[(k0+0 >= 0 && k0+0 < SZ) ? k0+0 : 0];
            if (k0+1 >= 0 && k0+1 < SZ) A += t.y * cgA[(k0+1 >= 0 && k0+1 < SZ) ? k0+1 : 0];
            if (k0+2 >= 0 && k0+2 < SZ) A += t.z * cgA[(k0+2 >= 0 && k0+2 < SZ) ? k0+2 : 0];
            if (k0+3 >= 0 && k0+3 < SZ) A += t.w * cgA[(k0+3 >= 0 && k0+3 < SZ) ? k0+3 : 0];
        }
        #pragma unroll
        for (int v = 0; v < NB; v++) {
            float4 t = pb[v];
            int k0 = 4*v - SB;
            if constexpr (STREAMB) {
                if (k0+0 >= 0 && k0+0 < SZ) B += t.x * cbs[(k0+0 >= 0 && k0+0 < SZ) ? k0+0 : 0];
                if (k0+1 >= 0 && k0+1 < SZ) B += t.y * cbs[(k0+1 >= 0 && k0+1 < SZ) ? k0+1 : 0];
                if (k0+2 >= 0 && k0+2 < SZ) B += t.z * cbs[(k0+2 >= 0 && k0+2 < SZ) ? k0+2 : 0];
                if (k0+3 >= 0 && k0+3 < SZ) B += t.w * cbs[(k0+3 >= 0 && k0+3 < SZ) ? k0+3 : 0];
            } else {
                if (k0+0 >= 0 && k0+0 < SZ) B += t.x * cgB[(k0+0 >= 0 && k0+0 < SZ) ? k0+0 : 0];
                if (k0+1 >= 0 && k0+1 < SZ) B += t.y * cgB[(k0+1 >= 0 && k0+1 < SZ) ? k0+1 : 0];
                if (k0+2 >= 0 && k0+2 < SZ) B += t.z * cgB[(k0+2 >= 0 && k0+2 < SZ) ? k0+2 : 0];
                if (k0+3 >= 0 && k0+3 < SZ) B += t.w * cgB[(k0+3 >= 0 && k0+3 < SZ) ? k0+3 : 0];
            }
        }
        int jp = __shfl_sync(FULLM, j, pr);
        int pp = __shfl_sync(FULLM, p, pr);
        if (lane < SZ) {
            float M = 0.5f * (A + B);
            out [(size_t)jp * (D1*D2) + (ROFF+li)*D2 + (COFF+lj)] = M;
            outT[(size_t)pp * (D1*D2) + (COFF+lj)*D1 + (ROFF+li)] = M;
        }
    }
}

// Shared warp prologue: canonical compaction + staging. Returns nv; fills j,p.
template<bool SAME>
__device__ __forceinline__ int prologue(int rel, const KP& P,
    const int* __restrict__ sel, int n,
    float* s_feA, float* s_feB, int lane, int& j, int& p)
{
    int base = rel * PAIRS;
    if (base >= n) return 0;
    int navail = min(PAIRS, n - base);

    int e = 0, ie = 0;
    bool v = false;
    j = 0; p = 0;
    if (lane < navail) {
        j  = base + lane;
        e  = __ldg(sel + j);
        ie = __ldg(P.einv + e);
        p  = g2b_scratch[ie];
        v  = SAME ? (p >= j) : true;
    }
    unsigned m = __ballot_sync(FULLM, v);
    int nv = __popc(m);
    if (nv == 0) return 0;
    int sl = (lane < nv) ? __fns(m, 0, lane + 1) : 0;
    j  = __shfl_sync(FULLM, j,  sl);
    e  = __shfl_sync(FULLM, e,  sl);
    ie = __shfl_sync(FULLM, ie, sl);
    p  = __shfl_sync(FULLM, p,  sl);

    for (int r = 0; r < 2 * nv; r++) {
        int pr = r >> 1;
        int eA = __shfl_sync(FULLM, e,  pr);
        int eB = __shfl_sync(FULLM, ie, pr);
        int edge = (r & 1) ? eB : eA;
        float* dst = ((r & 1) ? s_feB : s_feA) + pr * 100;
        int a  = __ldg(P.n1a + edge);
        int bb = __ldg(P.n2a + edge);
        bool self = false;
        if (a == bb) {
            float sx = __ldg(P.S + 3*edge), sy = __ldg(P.S + 3*edge + 1), sz = __ldg(P.S + 3*edge + 2);
            self = (sx*sx + sy*sy + sz*sz) < 1e-12f;
        }
        if (lane < 25) {
            float4 vv = __ldg((const float4*)(P.fe + (size_t)edge * 100) + lane);
            if (self) {
                float4 w = __ldg((const float4*)(P.fn + (size_t)a * 100) + lane);
                vv.x += w.x; vv.y += w.y; vv.z += w.z; vv.w += w.w;
            }
            ((float4*)dst)[lane] = vv;
        }
    }
    __syncwarp();
    return nv;
}

// ---------------- 11 list (D=10, EL=100) ----------------
__device__ __forceinline__ void ham11(int rel, const KP& P,
    const float* __restrict__ s_cg, float* s_feA, float* s_feB, int lane)
{
    int j, p;
    int nv = prologue<true>(rel, P, P.sel11, P.n11, s_feA, s_feB, lane, j, p);
    if (nv == 0) return;
    float* o = P.out11;

    // SZ=1: 4 blocks x 7 pairs = 28 lanes, one pass.
    {
        int pr = lane >> 2;
        if (pr > PAIRS - 1) pr = PAIRS - 1;
        int m = lane & 1, h = (lane >> 1) & 1;
        int koA = 10*h + m, koB = 10*m + h;
        float cg0 = s_cg[0];
        float A = s_feA[pr*100 + koA];
        float B = s_feB[pr*100 + koB];
        int jp = __shfl_sync(FULLM, j, pr);
        int pp = __shfl_sync(FULLM, p, pr);
        if (lane < 28 && pr < nv) {
            float M = 0.5f * cg0 * (A + B);
            o[(size_t)jp*100 + koA] = M;
            o[(size_t)pp*100 + koB] = M;
        }
    }
    // SZ=3: 4 blocks x 3 elems x 2 pairs = 24 lanes, 4 passes.
    {
        bool act = lane < 24;
        int sub = lane >= 12 ? 1 : 0;
        int r = (act ? lane : 0) - 12*sub;
        int b = r / 3, t = r - 3*b;
        int m = b & 1, h = b >> 1;
        int koA = h ? (20 + 3*m) : (2 + 10*m);
        int koB = h ? (2 + 10*m) : (20 + 3*m);
        int cA = (h ? 35 : 1) + 3*t;
        int cB = (h ? 1 : 35) + 3*t;
        int ob  = h ? (20 + m + 10*t) : (2 + 10*m + t);
        int otb = h ? (2 + 10*m + t) : (20 + m + 10*t);
        float a0=s_cg[cA], a1=s_cg[cA+1], a2=s_cg[cA+2];
        float b0=s_cg[cB], b1=s_cg[cB+1], b2=s_cg[cB+2];
        #pragma unroll
        for (int pb = 0; pb < 8; pb += 2) {
            if (pb >= nv) break;
            int pr = pb + sub;
            if (pr > PAIRS - 1) pr = PAIRS - 1;
            const float* fa = s_feA + pr*100 + koA;
            const float* fb = s_feB + pr*100 + koB;
            float A = fa[0]*a0 + fa[1]*a1 + fa[2]*a2;
            float B = fb[0]*b0 + fb[1]*b1 + fb[2]*b2;
            int jp = __shfl_sync(FULLM, j, pr);
            int pp = __shfl_sync(FULLM, p, pr);
            if (act && pb + sub < nv) {
                float M = 0.5f*(A+B);
                o[(size_t)jp*100 + ob ] = M;
                o[(size_t)pp*100 + otb] = M;
            }
        }
    }
    // SZ=5: 4 blocks x 5 = 20 lanes, per-pair passes.
    {
        bool act = lane < 20;
        int L = act ? lane : 0;
        int b = L / 5, t = L - 5*b;
        int m = b & 1, h = b >> 1;
        int koA = h ? (50 + 5*m) : (5 + 10*m);
        int koB = h ? (5 + 10*m) : (50 + 5*m);
        int cA = (h ? 350 : 10) + 5*t;
        int cB = (h ? 10 : 350) + 5*t;
        int ob  = h ? (50 + m + 10*t) : (5 + 10*m + t);
        int otb = h ? (5 + 10*m + t) : (50 + m + 10*t);
        float a0=s_cg[cA],a1=s_cg[cA+1],a2=s_cg[cA+2],a3=s_cg[cA+3],a4=s_cg[cA+4];
        float c0=s_cg[cB],c1=s_cg[cB+1],c2=s_cg[cB+2],c3=s_cg[cB+3],c4=s_cg[cB+4];
        #pragma unroll 2
        for (int pr = 0; pr < nv; pr++) {
            const float* fa = s_feA + pr*100 + koA;
            const float* fb = s_feB + pr*100 + koB;
            float A = fa[0]*a0 + fa[1]*a1 + fa[2]*a2 + fa[3]*a3 + fa[4]*a4;
            float B = fb[0]*c0 + fb[1]*c1 + fb[2]*c2 + fb[3]*c3 + fb[4]*c4;
            int jp = __shfl_sync(FULLM, j, pr);
            int pp = __shfl_sync(FULLM, p, pr);
            if (act) {
                float M = 0.5f*(A+B);
                o[(size_t)jp*100 + ob ] = M;
                o[(size_t)pp*100 + otb] = M;
            }
        }
    }
    // SZ=9: 1 block x 9 elems x 3 pairs = 27 lanes, 3 passes.
    {
        bool act = lane < 27;
        int L = act ? lane : 0;
        int sub = L / 9;
        int t = L - 9*sub;
        int li = t / 3, lj = t - 3*li;
        int cA = 44 + 9*t;
        int cB = 44 + 9*(3*lj + li);
        int ob  = 22 + 10*li + lj;
        int otb = 22 + 10*lj + li;
        float a[9], c[9];
        #pragma unroll
        for (int k = 0; k < 9; k++) { a[k] = s_cg[cA+k]; c[k] = s_cg[cB+k]; }
        #pragma unroll
        for (int pb = 0; pb < 9; pb += 3) {
            if (pb >= nv) break;
            int pr = pb + sub;
            if (pr > PAIRS - 1) pr = PAIRS - 1;
            const float* fa = s_feA + pr*100 + 26;
            const float* fb = s_feB + pr*100 + 26;
            float A = 0.f, B = 0.f;
            #pragma unroll
            for (int k = 0; k < 9; k++) { A += fa[k]*a[k]; B += fb[k]*c[k]; }
            int jp = __shfl_sync(FULLM, j, pr);
            int pp = __shfl_sync(FULLM, p, pr);
            if (act && pb + sub < nv) {
                float M = 0.5f*(A+B);
                o[(size_t)jp*100 + ob ] = M;
                o[(size_t)pp*100 + otb] = M;
            }
        }
    }
    // SZ=15 x2 (regs) and SZ=25 (streamed cgB).
    blk<1,2,2,3, 2,5, 10,10,false>(lane, nv, j, p, s_cg, s_feA, s_feB, o, o);
    blk<2,1,3,2, 5,2, 10,10,false>(lane, nv, j, p, s_cg, s_feA, s_feB, o, o);
    blk<2,2,3,3, 5,5, 10,10,true >(lane, nv, j, p, s_cg, s_feA, s_feB, o, o);
}

// ---------------- 01 list (D1=4, D2=10, EL=40) ----------------
__device__ __forceinline__ void ham01(int rel, const KP& P,
    const float* __restrict__ s_cg, float* s_feA, float* s_feB, int lane)
{
    int j, p;
    int nv = prologue<false>(rel, P, P.sel01, P.n01, s_feA, s_feB, lane, j, p);
    if (nv == 0) return;
    float* o  = P.out01;
    float* oT = P.out10;

    // SZ=1: 2 blocks x 7 pairs = 14 lanes.
    {
        int pr = lane >> 1;
        if (pr > PAIRS - 1) pr = PAIRS - 1;
        int m = lane & 1;
        int koA = m, koB = 10*m;
        float cg0 = s_cg[0];
        float A = s_feA[pr*100 + koA];
        float B = s_feB[pr*100 + koB];
        int jp = __shfl_sync(FULLM, j, pr);
        int pp = __shfl_sync(FULLM, p, pr);
        if (lane < 14 && pr < nv) {
            float M = 0.5f * cg0 * (A + B);
            o [(size_t)jp*40 + m  ] = M;
            oT[(size_t)pp*40 + 4*m] = M;
        }
    }
    // SZ=3: 3 blocks x 3 = 9 elems, 3 pairs/pass, 3 passes.
    {
        bool act = lane < 27;
        int L = act ? lane : 0;
        int sub = L / 9;
        int r = L - 9*sub;
        int b = r / 3, t = r - 3*b;
        bool b0 = (b == 0);
        int koA = b0 ? 2  : (b == 1 ? 20 : 23);
        int koB = b0 ? 20 : (b == 1 ? 2  : 12);
        int cA = (b0 ? 1 : 35) + 3*t;
        int cB = (b0 ? 35 : 1) + 3*t;
        int ob  = b0 ? (2 + t)   : (10 + 10*t + (b - 1));
        int otb = b0 ? (8 + 4*t) : ((b - 1)*4 + 1 + t);
        float a0=s_cg[cA],a1=s_cg[cA+1],a2=s_cg[cA+2];
        float c0=s_cg[cB],c1=s_cg[cB+1],c2=s_cg[cB+2];
        #pragma unroll
        for (int pb = 0; pb < 9; pb += 3) {
            if (pb >= nv) break;
            int pr = pb + sub;
            if (pr > PAIRS - 1) pr = PAIRS - 1;
            const float* fa = s_feA + pr*100 + koA;
            const float* fb = s_feB + pr*100 + koB;
            float A = fa[0]*a0 + fa[1]*a1 + fa[2]*a2;
            float B = fb[0]*c0 + fb[1]*c1 + fb[2]*c2;
            int jp = __shfl_sync(FULLM, j, pr);
            int pp = __shfl_sync(FULLM, p, pr);
            if (act && pb + sub < nv) {
                float M = 0.5f*(A+B);
                o [(size_t)jp*40 + ob ] = M;
                oT[(size_t)pp*40 + otb] = M;
            }
        }
    }
    // SZ=5: 1 block x 5 elems, 6 pairs/pass: 2 passes cover 12 >= 7.
    {
        int L = lane < 30 ? lane : 0;
        int sub = L / 5;
        int t = L - 5*sub;
        int cA = 10 + 5*t, cB = 350 + 5*t;
        int ob = 5 + t, otb = 20 + 4*t;
        float a0=s_cg[cA],a1=s_cg[cA+1],a2=s_cg[cA+2],a3=s_cg[cA+3],a4=s_cg[cA+4];
        float c0=s_cg[cB],c1=s_cg[cB+1],c2=s_cg[cB+2],c3=s_cg[cB+3],c4=s_cg[cB+4];
        #pragma unroll
        for (int pb = 0; pb < 12; pb += 6) {
            if (pb >= nv) break;
            int pr = pb + sub;
            if (pr > PAIRS - 1) pr = PAIRS - 1;
            const float* fa = s_feA + pr*100 + 5;
            const float* fb = s_feB + pr*100 + 50;
            float A = fa[0]*a0 + fa[1]*a1 + fa[2]*a2 + fa[3]*a3 + fa[4]*a4;
            float B = fb[0]*c0 + fb[1]*c1 + fb[2]*c2 + fb[3]*c3 + fb[4]*c4;
            int jp = __shfl_sync(FULLM, j, pr);
            int pp = __shfl_sync(FULLM, p, pr);
            if (lane < 30 && pb + sub < nv) {
                float M = 0.5f*(A+B);
                o [(size_t)jp*40 + ob ] = M;
                oT[(size_t)pp*40 + otb] = M;
            }
        }
    }
    // SZ=9: 1 block x 9 elems, 3 pairs/pass, 3 passes.
    {
        bool act = lane < 27;
        int L = act ? lane : 0;
        int sub = L / 9;
        int t = L - 9*sub;
        int li = t / 3, lj = t - 3*li;
        int cA = 44 + 9*t;
        int cB = 44 + 9*(3*lj + li);
        int ob  = 12 + 10*li + lj;
        int otb = 9 + 4*lj + li;
        float a[9], c[9];
        #pragma unroll
        for (int k = 0; k < 9; k++) { a[k] = s_cg[cA+k]; c[k] = s_cg[cB+k]; }
        #pragma unroll
        for (int pb = 0; pb < 9; pb += 3) {
            if (pb >= nv) break;
            int pr = pb + sub;
            if (pr > PAIRS - 1) pr = PAIRS - 1;
            const float* fa = s_feA + pr*100 + 26;
            const float* fb = s_feB + pr*100 + 26;
            float A = 0.f, B = 0.f;
            #pragma unroll
            for (int k = 0; k < 9; k++) { A += fa[k]*a[k]; B += fb[k]*c[k]; }
            int jp = __shfl_sync(FULLM, j, pr);
            int pp = __shfl_sync(FULLM, p, pr);
            if (act && pb + sub < nv) {
                float M = 0.5f*(A+B);
                o [(size_t)jp*40 + ob ] = M;
                oT[(size_t)pp*40 + otb] = M;
            }
        }
    }
    // SZ=15.
    blk<1,2,2,3, 1,5, 4,10,false>(lane, nv, j, p, s_cg, s_feA, s_feB, o, oT);
}

// ---------------- 00 list (D=4, EL=16) ----------------
__device__ __forceinline__ void ham00(int rel, const KP& P,
    const float* __restrict__ s_cg, float* s_feA, float* s_feB, int lane)
{
    int j, p;
    int nv = prologue<true>(rel, P, P.sel00, P.n00, s_feA, s_feB, lane, j, p);
    if (nv == 0) return;
    float* o = P.out00;

    // SZ=1: 1 block x 7 pairs = 7 lanes.
    {
        int pr = lane < PAIRS ? lane : 0;
        float cg0 = s_cg[0];
        float A = s_feA[pr*100];
        float B = s_feB[pr*100];
        if (lane < PAIRS && lane < nv) {
            float M = 0.5f * cg0 * (A + B);
            o[(size_t)j*16] = M;
            o[(size_t)p*16] = M;
        }
    }
    // SZ=3: 2 blocks x 3 = 6 elems, 4 pairs/pass, 2 passes.
    {
        bool act = lane < 24;
        int L = act ? lane : 0;
        int sub = L / 6;
        int r = L - 6*sub;
        int h = r >= 3 ? 1 : 0;
        int t = r - 3*h;
        int koA = h ? 20 : 2;
        int koB = h ? 2 : 20;
        int cA = (h ? 35 : 1) + 3*t;
        int cB = (h ? 1 : 35) + 3*t;
        int ob  = h ? (4 + 4*t) : (1 + t);
        int otb = h ? (1 + t)   : (4 + 4*t);
        float a0=s_cg[cA],a1=s_cg[cA+1],a2=s_cg[cA+2];
        float c0=s_cg[cB],c1=s_cg[cB+1],c2=s_cg[cB+2];
        #pragma unroll
        for (int pb = 0; pb < 8; pb += 4) {
            if (pb >= nv) break;
            int pr = pb + sub;
            if (pr > PAIRS - 1) pr = PAIRS - 1;
            const float* fa = s_feA + pr*100 + koA;
            const float* fb = s_feB + pr*100 + koB;
            float A = fa[0]*a0 + fa[1]*a1 + fa[2]*a2;
            float B = fb[0]*c0 + fb[1]*c1 + fb[2]*c2;
            int jp = __shfl_sync(FULLM, j, pr);
            int pp = __shfl_sync(FULLM, p, pr);
            if (act && pb + sub < nv) {
                float M = 0.5f*(A+B);
                o[(size_t)jp*16 + ob ] = M;
                o[(size_t)pp*16 + otb] = M;
            }
        }
    }
    // SZ=9: 1 block, 3 pairs/pass, 3 passes.
    {
        bool act = lane < 27;
        int L = act ? lane : 0;
        int sub = L / 9;
        int t = L - 9*sub;
        int li = t / 3, lj = t - 3*li;
        int cA = 44 + 9*t;
        int cB = 44 + 9*(3*lj + li);
        int ob  = 5 + 4*li + lj;
        int otb = 5 + 4*lj + li;
        float a[9], c[9];
        #pragma unroll
        for (int k = 0; k < 9; k++) { a[k] = s_cg[cA+k]; c[k] = s_cg[cB+k]; }
        #pragma unroll
        for (int pb = 0; pb < 9; pb += 3) {
            if (pb >= nv) break;
            int pr = pb + sub;
            if (pr > PAIRS - 1) pr = PAIRS - 1;
            const float* fa = s_feA + pr*100 + 26;
            const float* fb = s_feB + pr*100 + 26;
            float A = 0.f, B = 0.f;
            #pragma unroll
            for (int k = 0; k < 9; k++) { A += fa[k]*a[k]; B += fb[k]*c[k]; }
            int jp = __shfl_sync(FULLM, j, pr);
            int pp = __shfl_sync(FULLM, p, pr);
            if (act && pb + sub < nv) {
                float M = 0.5f*(A+B);
                o[(size_t)jp*16 + ob ] = M;
                o[(size_t)pp*16 + otb] = M;
            }
        }
    }
}

__global__ __launch_bounds__(128, 8) void fused_kernel(KP P) {
    __shared__ __align__(16) float s_cg[(CG_TOTAL + 3) & ~3];
    __shared__ __align__(16) float s_fe[WARPS * 2 * PAIRS * 100];
    load_cg_shared(s_cg, P);
    __syncthreads();

    int warp = threadIdx.x >> 5, lane = threadIdx.x & 31;
    float* s_feA = s_fe + warp * (2 * PAIRS * 100);
    float* s_feB = s_feA + PAIRS * 100;
    int gw = blockIdx.x * WARPS + warp;

    if (gw < P.b1)       ham00(gw,        P, s_cg, s_feA, s_feB, lane);
    else if (gw < P.b2)  ham01(gw - P.b1, P, s_cg, s_feA, s_feB, lane);
    else if (gw < P.b3)  ham11(gw - P.b2, P, s_cg, s_feA, s_feB, lane);
}

extern "C" void kernel_launch(void* const* d_in, const int* in_sizes, int n_in,
                              void* d_out, int out_size) {
    KP P;
    P.fn   = (const float*)d_in[0];
    P.fe   = (const float*)d_in[1];
    P.S    = (const float*)d_in[2];
    const int* eidx = (const int*)d_in[3];
    P.einv = (const int*)d_in[5];
    for (int i = 0; i < 9; i++) P.cg[i] = (const float*)d_in[6 + i];
    P.sel00 = (const int*)d_in[15]; P.n00 = in_sizes[15];
    P.sel01 = (const int*)d_in[16]; P.n01 = in_sizes[16];
    const int* sel10 = (const int*)d_in[17]; int n10 = in_sizes[17];
    P.sel11 = (const int*)d_in[18]; P.n11 = in_sizes[18];

    int E = in_sizes[1] / 100;
    P.n1a = eidx;
    P.n2a = eidx + E;

    float* out = (float*)d_out;
    P.out00 = out;
    P.out01 = P.out00 + 16LL  * P.n00;
    P.out10 = P.out01 + 40LL  * P.n01;
    P.out11 = P.out10 + 40LL  * n10;
    float* outg = P.out11 + 100LL * P.n11;

    int w00 = (P.n00 + PAIRS - 1) / PAIRS;
    int w01 = (P.n01 + PAIRS - 1) / PAIRS;
    int w11 = (P.n11 + PAIRS - 1) / PAIRS;
    P.b1 = w00; P.b2 = P.b1 + w01; P.b3 = P.b2 + w11;

    int tot = P.n00 + P.n01 + n10 + P.n11;
    if (tot) g2b_kernel<<<(tot + 255) / 256, 256>>>(P.sel00, P.n00, P.sel01, P.n01,
                                                    sel10, n10, P.sel11, P.n11, outg);
    int blocks = (P.b3 + WARPS - 1) / WARPS;
    if (blocks) fused_kernel<<<blocks, 128>>>(P);

    (void)n_in; (void)out_size;
}

// round 12
// speedup vs baseline: 2.1422x; 1.2584x over previous
#include <cuda_runtime.h>

#define CG_TOTAL 1225
#define PAIRS 7
#define WARPS 4   // 128 threads/block, 28 candidate pairs per block
#define FULLM 0xffffffffu

__constant__ int c_cgoff[9] = {0,1,10,35,44,125,350,375,600};

__host__ __device__ constexpr int PFX(int b) {
    const int t[16] = {0,1,2,5,10,11,12,15,20,23,26,35,50,55,60,75};
    return t[b];
}
__host__ __device__ constexpr int CGO(int p) {
    const int t[9] = {0,1,10,35,44,125,350,375,600};
    return t[p];
}

__device__ int g2b_scratch[524288];

struct KP {
    const float *fe, *fn;
    const int *n1a, *einv;
    const float* cg[9];
    const int *sel00, *sel01, *sel11;
    int n00, n01, n11;
    int b1, b2, b3;
    float *out00, *out01, *out10, *out11;
};

__global__ void g2b_kernel(const int* __restrict__ s00, int n00,
                           const int* __restrict__ s01, int n01,
                           const int* __restrict__ s10, int n10,
                           const int* __restrict__ s11, int n11,
                           float* __restrict__ outg)
{
    int total = n00 + n01 + n10 + n11;
    for (int t = blockIdx.x * blockDim.x + threadIdx.x; t < total;
         t += gridDim.x * blockDim.x) {
        const int* s; int loc;
        if (t < n00)                  { s = s00; loc = t; }
        else if (t < n00 + n01)       { s = s01; loc = t - n00; }
        else if (t < n00 + n01 + n10) { s = s10; loc = t - n00 - n01; }
        else                          { s = s11; loc = t - n00 - n01 - n10; }
        int e = __ldg(s + loc);
        g2b_scratch[e] = loc;
        outg[e] = (float)loc;
    }
}

__device__ __forceinline__ void load_cg_shared(float* s_cg, const KP& P) {
    for (int t = threadIdx.x; t < CG_TOTAL; t += blockDim.x) {
        int p = 0;
        #pragma unroll
        for (int q = 1; q < 9; q++) if (t >= c_cgoff[q]) p = q;
        s_cg[t] = __ldg(P.cg[p] + (t - c_cgoff[p]));
    }
}

// Cross-list block pass (cgB form), float4 broadcast fe reads. Used by ham01 SZ=15.
template<int L1,int L2,int AM1,int AM2,int ROFF,int COFF,int D1,int D2>
__device__ __forceinline__ void blk(int lane, int nv, int j, int p,
    const float* __restrict__ s_cg,
    const float* __restrict__ s_feA, const float* __restrict__ s_feB,
    float* __restrict__ out, float* __restrict__ outT)
{
    constexpr int W1 = 2*L1+1, W2 = 2*L2+1, SZ = W1*W2;
    constexpr int offA = PFX(4*AM1+AM2), offB = PFX(4*AM2+AM1);
    constexpr int A0 = offA & ~3, B0 = offB & ~3;
    constexpr int SA = offA - A0, SB = offB - B0;
    constexpr int NA = (SA + SZ + 3) / 4, NB = (SB + SZ + 3) / 4;

    int li = lane / W2, lj = lane % W2;
    float cgA[SZ], cgB[SZ];
    if (lane < SZ) {
        const float* ca = s_cg + CGO(L1*3+L2) + lane * SZ;
        const float* cb = s_cg + CGO(L2*3+L1) + (lj*W1+li) * SZ;
        #pragma unroll
        for (int k = 0; k < SZ; k++) cgA[k] = ca[k];
        #pragma unroll
        for (int k = 0; k < SZ; k++) cgB[k] = cb[k];
    }
    #pragma unroll 2
    for (int pr = 0; pr < nv; pr++) {
        const float4* pa = (const float4*)(s_feA + pr*100 + A0);
        const float4* pb = (const float4*)(s_feB + pr*100 + B0);
        float A = 0.f, B = 0.f;
        #pragma unroll
        for (int v = 0; v < NA; v++) {
            float4 t = pa[v];
            int k0 = 4*v - SA;
            if (k0+0 >= 0 && k0+0 < SZ) A += t.x * cgA[(k0+0 >= 0 && k0+0 < SZ) ? k0+0 : 0];
            if (k0+1 >= 0 && k0+1 < SZ) A += t.y * cgA[(k0+1 >= 0 && k0+1 < SZ) ? k0+1 : 0];
            if (k0+2 >= 0 && k0+2 < SZ) A += t.z * cgA[(k0+2 >= 0 && k0+2 < SZ) ? k0+2 : 0];
            if (k0+3 >= 0 && k0+3 < SZ) A += t.w * cgA[(k0+3 >= 0 && k0+3 < SZ) ? k0+3 : 0];
        }
        #pragma unroll
        for (int v = 0; v < NB; v++) {
            float4 t = pb[v];
            int k0 = 4*v - SB;
            if (k0+0 >= 0 && k0+0 < SZ) B += t.x * cgB[(k0+0 >= 0 && k0+0 < SZ) ? k0+0 : 0];
            if (k0+1 >= 0 && k0+1 < SZ) B += t.y * cgB[(k0+1 >= 0 && k0+1 < SZ) ? k0+1 : 0];
            if (k0+2 >= 0 && k0+2 < SZ) B += t.z * cgB[(k0+2 >= 0 && k0+2 < SZ) ? k0+2 : 0];
            if (k0+3 >= 0 && k0+3 < SZ) B += t.w * cgB[(k0+3 >= 0 && k0+3 < SZ) ? k0+3 : 0];
        }
        int jp = __shfl_sync(FULLM, j, pr);
        int pp = __shfl_sync(FULLM, p, pr);
        if (lane < SZ) {
            float M = 0.5f * (A + B);
            out [jp * (unsigned)(D1*D2) + (ROFF+li)*D2 + (COFF+lj)] = M;
            outT[pp * (unsigned)(D1*D2) + (COFF+lj)*D1 + (ROFF+li)] = M;
        }
    }
}

// Shared warp prologue: canonical compaction + staging. self <=> e == inv(e).
template<bool SAME>
__device__ __forceinline__ int prologue(int rel, const KP& P,
    const int* __restrict__ sel, int n,
    float* s_feA, float* s_feB, int lane, int& j, int& p)
{
    int base = rel * PAIRS;
    if (base >= n) return 0;
    int navail = min(PAIRS, n - base);

    int e = 0, ie = 0;
    bool v = false;
    j = 0; p = 0;
    if (lane < navail) {
        j  = base + lane;
        e  = __ldg(sel + j);
        ie = __ldg(P.einv + e);
        p  = g2b_scratch[ie];
        v  = SAME ? (p >= j) : true;
    }
    unsigned m = __ballot_sync(FULLM, v);
    int nv = __popc(m);
    if (nv == 0) return 0;
    int sl = (lane < nv) ? __fns(m, 0, lane + 1) : 0;
    j  = __shfl_sync(FULLM, j,  sl);
    e  = __shfl_sync(FULLM, e,  sl);
    ie = __shfl_sync(FULLM, ie, sl);
    p  = __shfl_sync(FULLM, p,  sl);

    for (int r = 0; r < 2 * nv; r++) {
        int pr = r >> 1;
        int eA = __shfl_sync(FULLM, e,  pr);
        int eB = __shfl_sync(FULLM, ie, pr);
        int edge = (r & 1) ? eB : eA;
        bool self = (eA == eB);
        float* dst = ((r & 1) ? s_feB : s_feA) + pr * 100;
        if (lane < 25) {
            float4 vv = __ldg((const float4*)(P.fe + (size_t)edge * 100) + lane);
            if (self) {
                int a = __ldg(P.n1a + edge);
                float4 w = __ldg((const float4*)(P.fn + (size_t)a * 100) + lane);
                vv.x += w.x; vv.y += w.y; vv.z += w.z; vv.w += w.w;
            }
            ((float4*)dst)[lane] = vv;
        }
    }
    __syncwarp();
    return nv;
}

// ---------------- 11 list (D=10, EL=100) — symmetry-shuffle form ----------------
__device__ __forceinline__ void ham11(int rel, const KP& P,
    const float* __restrict__ s_cg, float* s_feA, float* s_feB, int lane)
{
    int j, p;
    int nv = prologue<true>(rel, P, P.sel11, P.n11, s_feA, s_feB, lane, j, p);
    if (nv == 0) return;
    float* o = P.out11;

    // SZ=1: 4 blocks x 7 pairs = 28 lanes, one pass.
    {
        int pr = lane >> 2; if (pr > PAIRS - 1) pr = PAIRS - 1;
        int m = lane & 1, h = (lane >> 1) & 1;
        int ko = 10*h + m;
        int y = (pr << 2) | (m << 1) | h;
        float cg0 = s_cg[0];
        float A1 = s_feA[pr*100 + ko];
        float A2 = s_feB[pr*100 + ko];
        float B1 = __shfl_sync(FULLM, A2, y);
        float B2 = __shfl_sync(FULLM, A1, y);
        int jp = __shfl_sync(FULLM, j, pr);
        int pp = __shfl_sync(FULLM, p, pr);
        if (lane < 28 && pr < nv) {
            o[jp * 100u + ko] = 0.5f * cg0 * (A1 + B1);
            o[pp * 100u + ko] = 0.5f * cg0 * (A2 + B2);
        }
    }
    // SZ=3: 4 blocks x 3 elems x 2 pair-subs = 24 lanes, 4 passes.
    {
        bool act = lane < 24;
        int L = act ? lane : 0;
        int sub = L >= 12 ? 1 : 0;
        int r = L - 12*sub;
        int b = r / 3, t = r - 3*b;
        int m = b & 1, h = b >> 1;
        int ko = h ? (20 + 3*m) : (2 + 10*m);
        int cA = (h ? 35 : 1) + 3*t;
        int ob = h ? (20 + m + 10*t) : (2 + 10*m + t);
        int y  = 12*sub + ((r + 6) % 12);
        float a0=s_cg[cA], a1=s_cg[cA+1], a2=s_cg[cA+2];
        #pragma unroll
        for (int pb = 0; pb < 8; pb += 2) {
            if (pb >= nv) break;
            int pr = pb + sub; if (pr > PAIRS - 1) pr = PAIRS - 1;
            const float* fa = s_feA + pr*100 + ko;
            const float* fb = s_feB + pr*100 + ko;
            float A1 = fa[0]*a0 + fa[1]*a1 + fa[2]*a2;
            float A2 = fb[0]*a0 + fb[1]*a1 + fb[2]*a2;
            float B1 = __shfl_sync(FULLM, A2, y);
            float B2 = __shfl_sync(FULLM, A1, y);
            int jp = __shfl_sync(FULLM, j, pr);
            int pp = __shfl_sync(FULLM, p, pr);
            if (act && pb + sub < nv) {
                o[jp * 100u + ob] = 0.5f*(A1 + B1);
                o[pp * 100u + ob] = 0.5f*(A2 + B2);
            }
        }
    }
    // SZ=5: 4 blocks x 5 = 20 lanes, per-pair passes.
    {
        bool act = lane < 20;
        int L = act ? lane : 0;
        int b = L / 5, t = L - 5*b;
        int m = b & 1, h = b >> 1;
        int ko = h ? (50 + 5*m) : (5 + 10*m);
        int cA = (h ? 350 : 10) + 5*t;
        int ob = h ? (50 + m + 10*t) : (5 + 10*m + t);
        int y  = (L + 10) % 20;
        float a0=s_cg[cA],a1=s_cg[cA+1],a2=s_cg[cA+2],a3=s_cg[cA+3],a4=s_cg[cA+4];
        #pragma unroll 2
        for (int pr = 0; pr < nv; pr++) {
            const float* fa = s_feA + pr*100 + ko;
            const float* fb = s_feB + pr*100 + ko;
            float A1 = fa[0]*a0 + fa[1]*a1 + fa[2]*a2 + fa[3]*a3 + fa[4]*a4;
            float A2 = fb[0]*a0 + fb[1]*a1 + fb[2]*a2 + fb[3]*a3 + fb[4]*a4;
            float B1 = __shfl_sync(FULLM, A2, y);
            float B2 = __shfl_sync(FULLM, A1, y);
            int jp = __shfl_sync(FULLM, j, pr);
            int pp = __shfl_sync(FULLM, p, pr);
            if (act) {
                o[jp * 100u + ob] = 0.5f*(A1 + B1);
                o[pp * 100u + ob] = 0.5f*(A2 + B2);
            }
        }
    }
    // SZ=9: diagonal block, 3 pair-subs x 9 = 27 lanes, 3 passes.
    {
        bool act = lane < 27;
        int L = act ? lane : 0;
        int sub = L / 9;
        int t = L - 9*sub;
        int li = t / 3, lj = t - 3*li;
        int cA = 44 + 9*t;
        int ob = 22 + 10*li + lj;
        int y  = 9*sub + 3*lj + li;
        float a[9];
        #pragma unroll
        for (int k = 0; k < 9; k++) a[k] = s_cg[cA+k];
        #pragma unroll
        for (int pb = 0; pb < 9; pb += 3) {
            if (pb >= nv) break;
            int pr = pb + sub; if (pr > PAIRS - 1) pr = PAIRS - 1;
            const float* fa = s_feA + pr*100 + 26;
            const float* fb = s_feB + pr*100 + 26;
            float A1 = 0.f, A2 = 0.f;
            #pragma unroll
            for (int k = 0; k < 9; k++) { A1 += fa[k]*a[k]; A2 += fb[k]*a[k]; }
            float B1 = __shfl_sync(FULLM, A2, y);
            float B2 = __shfl_sync(FULLM, A1, y);
            int jp = __shfl_sync(FULLM, j, pr);
            int pp = __shfl_sync(FULLM, p, pr);
            if (act && pb + sub < nv) {
                o[jp * 100u + ob] = 0.5f*(A1 + B1);
                o[pp * 100u + ob] = 0.5f*(A2 + B2);
            }
        }
    }
    // SZ=15 packed: blocks (2,3)+(3,2), 30 lanes, one pass per pair.
    {
        bool act = lane < 30;
        int L = act ? lane : 0;
        int g = L >= 15 ? 1 : 0;
        int t = L - 15*g;
        int li0 = t/5, lj0 = t - 5*li0;
        int li1 = t/3, lj1 = t - 3*li1;
        int li = g ? li1 : li0, lj = g ? lj1 : lj0;
        int ko = g ? 60 : 35;
        int cA = (g ? 375 : 125) + 15*t;
        int ob = (g ? 52 : 25) + 10*li + lj;
        int y  = g ? (lj*5 + li) : (15 + lj*3 + li);
        float a[15];
        #pragma unroll
        for (int k = 0; k < 15; k++) a[k] = s_cg[cA+k];
        #pragma unroll 2
        for (int pr = 0; pr < nv; pr++) {
            const float* fa = s_feA + pr*100 + ko;
            const float* fb = s_feB + pr*100 + ko;
            float A1 = 0.f, A2 = 0.f;
            #pragma unroll
            for (int k = 0; k < 15; k++) { A1 += fa[k]*a[k]; A2 += fb[k]*a[k]; }
            float B1 = __shfl_sync(FULLM, A2, y);
            float B2 = __shfl_sync(FULLM, A1, y);
            int jp = __shfl_sync(FULLM, j, pr);
            int pp = __shfl_sync(FULLM, p, pr);
            if (act) {
                o[jp * 100u + ob] = 0.5f*(A1 + B1);
                o[pp * 100u + ob] = 0.5f*(A2 + B2);
            }
        }
    }
    // SZ=25: diagonal block (3,3), 25 lanes, f4 reads (base 72, shift 3).
    {
        bool act = lane < 25;
        int L = act ? lane : 0;
        int li = L / 5, lj = L - 5*li;
        int cA = 600 + 25*L;
        int ob = 55 + 10*li + lj;
        int y  = 5*lj + li;
        float a[25];
        if (act) {
            #pragma unroll
            for (int k = 0; k < 25; k++) a[k] = s_cg[cA+k];
        }
        #pragma unroll 2
        for (int pr = 0; pr < nv; pr++) {
            const float4* pa = (const float4*)(s_feA + pr*100 + 72);
            const float4* pb = (const float4*)(s_feB + pr*100 + 72);
            float A1 = 0.f, A2 = 0.f;
            #pragma unroll
            for (int v = 0; v < 7; v++) {
                float4 ta = pa[v];
                float4 tb = pb[v];
                int k0 = 4*v - 3;
                if (k0+0 >= 0 && k0+0 < 25) { float c = a[(k0+0>=0&&k0+0<25)?k0+0:0]; A1 += ta.x*c; A2 += tb.x*c; }
                if (k0+1 >= 0 && k0+1 < 25) { float c = a[(k0+1>=0&&k0+1<25)?k0+1:0]; A1 += ta.y*c; A2 += tb.y*c; }
                if (k0+2 >= 0 && k0+2 < 25) { float c = a[(k0+2>=0&&k0+2<25)?k0+2:0]; A1 += ta.z*c; A2 += tb.z*c; }
                if (k0+3 >= 0 && k0+3 < 25) { float c = a[(k0+3>=0&&k0+3<25)?k0+3:0]; A1 += ta.w*c; A2 += tb.w*c; }
            }
            float B1 = __shfl_sync(FULLM, A2, y);
            float B2 = __shfl_sync(FULLM, A1, y);
            int jp = __shfl_sync(FULLM, j, pr);
            int pp = __shfl_sync(FULLM, p, pr);
            if (act) {
                o[jp * 100u + ob] = 0.5f*(A1 + B1);
                o[pp * 100u + ob] = 0.5f*(A2 + B2);
            }
        }
    }
}

// ---------------- 01 list (D1=4, D2=10, EL=40) — cgB form ----------------
__device__ __forceinline__ void ham01(int rel, const KP& P,
    const float* __restrict__ s_cg, float* s_feA, float* s_feB, int lane)
{
    int j, p;
    int nv = prologue<false>(rel, P, P.sel01, P.n01, s_feA, s_feB, lane, j, p);
    if (nv == 0) return;
    float* o  = P.out01;
    float* oT = P.out10;

    // SZ=1: 2 blocks x 7 pairs = 14 lanes.
    {
        int pr = lane >> 1; if (pr > PAIRS - 1) pr = PAIRS - 1;
        int m = lane & 1;
        float cg0 = s_cg[0];
        float A = s_feA[pr*100 + m];
        float B = s_feB[pr*100 + 10*m];
        int jp = __shfl_sync(FULLM, j, pr);
        int pp = __shfl_sync(FULLM, p, pr);
        if (lane < 14 && pr < nv) {
            float M = 0.5f * cg0 * (A + B);
            o [jp * 40u + m  ] = M;
            oT[pp * 40u + 4*m] = M;
        }
    }
    // SZ=3: 3 blocks x 3 = 9 elems, 3 pair-subs, 3 passes.
    {
        bool act = lane < 27;
        int L = act ? lane : 0;
        int sub = L / 9;
        int r = L - 9*sub;
        int b = r / 3, t = r - 3*b;
        bool b0 = (b == 0);
        int koA = b0 ? 2  : (b == 1 ? 20 : 23);
        int koB = b0 ? 20 : (b == 1 ? 2  : 12);
        int cA = (b0 ? 1 : 35) + 3*t;
        int cB = (b0 ? 35 : 1) + 3*t;
        int ob  = b0 ? (2 + t)   : (10 + 10*t + (b - 1));
        int otb = b0 ? (8 + 4*t) : ((b - 1)*4 + 1 + t);
        float a0=s_cg[cA],a1=s_cg[cA+1],a2=s_cg[cA+2];
        float c0=s_cg[cB],c1=s_cg[cB+1],c2=s_cg[cB+2];
        #pragma unroll
        for (int pb = 0; pb < 9; pb += 3) {
            if (pb >= nv) break;
            int pr = pb + sub; if (pr > PAIRS - 1) pr = PAIRS - 1;
            const float* fa = s_feA + pr*100 + koA;
            const float* fb = s_feB + pr*100 + koB;
            float A = fa[0]*a0 + fa[1]*a1 + fa[2]*a2;
            float B = fb[0]*c0 + fb[1]*c1 + fb[2]*c2;
            int jp = __shfl_sync(FULLM, j, pr);
            int pp = __shfl_sync(FULLM, p, pr);
            if (act && pb + sub < nv) {
                float M = 0.5f*(A+B);
                o [jp * 40u + ob ] = M;
                oT[pp * 40u + otb] = M;
            }
        }
    }
    // SZ=5: 1 block x 5 elems, 6 pair-subs, 2 passes.
    {
        int L = lane < 30 ? lane : 0;
        int sub = L / 5;
        int t = L - 5*sub;
        int cA = 10 + 5*t, cB = 350 + 5*t;
        int ob = 5 + t, otb = 20 + 4*t;
        float a0=s_cg[cA],a1=s_cg[cA+1],a2=s_cg[cA+2],a3=s_cg[cA+3],a4=s_cg[cA+4];
        float c0=s_cg[cB],c1=s_cg[cB+1],c2=s_cg[cB+2],c3=s_cg[cB+3],c4=s_cg[cB+4];
        #pragma unroll
        for (int pb = 0; pb < 12; pb += 6) {
            if (pb >= nv) break;
            int pr = pb + sub; if (pr > PAIRS - 1) pr = PAIRS - 1;
            const float* fa = s_feA + pr*100 + 5;
            const float* fb = s_feB + pr*100 + 50;
            float A = fa[0]*a0 + fa[1]*a1 + fa[2]*a2 + fa[3]*a3 + fa[4]*a4;
            float B = fb[0]*c0 + fb[1]*c1 + fb[2]*c2 + fb[3]*c3 + fb[4]*c4;
            int jp = __shfl_sync(FULLM, j, pr);
            int pp = __shfl_sync(FULLM, p, pr);
            if (lane < 30 && pb + sub < nv) {
                float M = 0.5f*(A+B);
                o [jp * 40u + ob ] = M;
                oT[pp * 40u + otb] = M;
            }
        }
    }
    // SZ=9: 1 block x 9 elems, 3 pair-subs, 3 passes.
    {
        bool act = lane < 27;
        int L = act ? lane : 0;
        int sub = L / 9;
        int t = L - 9*sub;
        int li = t / 3, lj = t - 3*li;
        int cA = 44 + 9*t;
        int cB = 44 + 9*(3*lj + li);
        int ob  = 12 + 10*li + lj;
        int otb = 9 + 4*lj + li;
        float a[9], c[9];
        #pragma unroll
        for (int k = 0; k < 9; k++) { a[k] = s_cg[cA+k]; c[k] = s_cg[cB+k]; }
        #pragma unroll
        for (int pb = 0; pb < 9; pb += 3) {
            if (pb >= nv) break;
            int pr = pb + sub; if (pr > PAIRS - 1) pr = PAIRS - 1;
            const float* fa = s_feA + pr*100 + 26;
            const float* fb = s_feB + pr*100 + 26;
            float A = 0.f, B = 0.f;
            #pragma unroll
            for (int k = 0; k < 9; k++) { A += fa[k]*a[k]; B += fb[k]*c[k]; }
            int jp = __shfl_sync(FULLM, j, pr);
            int pp = __shfl_sync(FULLM, p, pr);
            if (act && pb + sub < nv) {
                float M = 0.5f*(A+B);
                o [jp * 40u + ob ] = M;
                oT[pp * 40u + otb] = M;
            }
        }
    }
    // SZ=15.
    blk<1,2,2,3, 1,5, 4,10>(lane, nv, j, p, s_cg, s_feA, s_feB, o, oT);
}

// ---------------- 00 list (D=4, EL=16) — symmetry-shuffle form ----------------
__device__ __forceinline__ void ham00(int rel, const KP& P,
    const float* __restrict__ s_cg, float* s_feA, float* s_feB, int lane)
{
    int j, p;
    int nv = prologue<true>(rel, P, P.sel00, P.n00, s_feA, s_feB, lane, j, p);
    if (nv == 0) return;
    float* o = P.out00;

    // SZ=1: diagonal block (0,0), 7 lanes.
    {
        int pr = lane < PAIRS ? lane : 0;
        float cg0 = s_cg[0];
        float A1 = s_feA[pr*100];
        float A2 = s_feB[pr*100];
        if (lane < PAIRS && lane < nv) {
            float M = 0.5f * cg0 * (A1 + A2);
            o[j * 16u] = M;
            o[p * 16u] = M;
        }
    }
    // SZ=3: blocks (0,2)+(2,0), 6 elems x 4 pair-subs = 24 lanes, 2 passes.
    {
        bool act = lane < 24;
        int L = act ? lane : 0;
        int sub = L / 6;
        int r = L - 6*sub;
        int h = r >= 3 ? 1 : 0;
        int t = r - 3*h;
        int ko = h ? 20 : 2;
        int cA = (h ? 35 : 1) + 3*t;
        int ob = h ? (4 + 4*t) : (1 + t);
        int y  = 6*sub + ((r + 3) % 6);
        float a0=s_cg[cA],a1=s_cg[cA+1],a2=s_cg[cA+2];
        #pragma unroll
        for (int pb = 0; pb < 8; pb += 4) {
            if (pb >= nv) break;
            int pr = pb + sub; if (pr > PAIRS - 1) pr = PAIRS - 1;
            const float* fa = s_feA + pr*100 + ko;
            const float* fb = s_feB + pr*100 + ko;
            float A1 = fa[0]*a0 + fa[1]*a1 + fa[2]*a2;
            float A2 = fb[0]*a0 + fb[1]*a1 + fb[2]*a2;
            float B1 = __shfl_sync(FULLM, A2, y);
            float B2 = __shfl_sync(FULLM, A1, y);
            int jp = __shfl_sync(FULLM, j, pr);
            int pp = __shfl_sync(FULLM, p, pr);
            if (act && pb + sub < nv) {
                o[jp * 16u + ob] = 0.5f*(A1 + B1);
                o[pp * 16u + ob] = 0.5f*(A2 + B2);
            }
        }
    }
    // SZ=9: diagonal block (2,2), 3 pair-subs x 9 = 27 lanes, 3 passes.
    {
        bool act = lane < 27;
        int L = act ? lane : 0;
        int sub = L / 9;
        int t = L - 9*sub;
        int li = t / 3, lj = t - 3*li;
        int cA = 44 + 9*t;
        int ob = 5 + 4*li + lj;
        int y  = 9*sub + 3*lj + li;
        float a[9];
        #pragma unroll
        for (int k = 0; k < 9; k++) a[k] = s_cg[cA+k];
        #pragma unroll
        for (int pb = 0; pb < 9; pb += 3) {
            if (pb >= nv) break;
            int pr = pb + sub; if (pr > PAIRS - 1) pr = PAIRS - 1;
            const float* fa = s_feA + pr*100 + 26;
            const float* fb = s_feB + pr*100 + 26;
            float A1 = 0.f, A2 = 0.f;
            #pragma unroll
            for (int k = 0; k < 9; k++) { A1 += fa[k]*a[k]; A2 += fb[k]*a[k]; }
            float B1 = __shfl_sync(FULLM, A2, y);
            float B2 = __shfl_sync(FULLM, A1, y);
            int jp = __shfl_sync(FULLM, j, pr);
            int pp = __shfl_sync(FULLM, p, pr);
            if (act && pb + sub < nv) {
                o[jp * 16u + ob] = 0.5f*(A1 + B1);
                o[pp * 16u + ob] = 0.5f*(A2 + B2);
            }
        }
    }
}

__global__ __launch_bounds__(128, 8) void fused_kernel(KP P) {
    __shared__ __align__(16) float s_cg[(CG_TOTAL + 3) & ~3];
    __shared__ __align__(16) float s_fe[WARPS * 2 * PAIRS * 100];
    load_cg_shared(s_cg, P);
    __syncthreads();

    int warp = threadIdx.x >> 5, lane = threadIdx.x & 31;
    float* s_feA = s_fe + warp * (2 * PAIRS * 100);
    float* s_feB = s_feA + PAIRS * 100;
    int gw = blockIdx.x * WARPS + warp;

    if (gw < P.b1)       ham00(gw,        P, s_cg, s_feA, s_feB, lane);
    else if (gw < P.b2)  ham01(gw - P.b1, P, s_cg, s_feA, s_feB, lane);
    else if (gw < P.b3)  ham11(gw - P.b2, P, s_cg, s_feA, s_feB, lane);
}

extern "C" void kernel_launch(void* const* d_in, const int* in_sizes, int n_in,
                              void* d_out, int out_size) {
    KP P;
    P.fn   = (const float*)d_in[0];
    P.fe   = (const float*)d_in[1];
    const int* eidx = (const int*)d_in[3];
    P.einv = (const int*)d_in[5];
    for (int i = 0; i < 9; i++) P.cg[i] = (const float*)d_in[6 + i];
    P.sel00 = (const int*)d_in[15]; P.n00 = in_sizes[15];
    P.sel01 = (const int*)d_in[16]; P.n01 = in_sizes[16];
    const int* sel10 = (const int*)d_in[17]; int n10 = in_sizes[17];
    P.sel11 = (const int*)d_in[18]; P.n11 = in_sizes[18];

    int E = in_sizes[1] / 100;
    P.n1a = eidx;

    float* out = (float*)d_out;
    P.out00 = out;
    P.out01 = P.out00 + 16LL  * P.n00;
    P.out10 = P.out01 + 40LL  * P.n01;
    P.out11 = P.out10 + 40LL  * n10;
    float* outg = P.out11 + 100LL * P.n11;

    int w00 = (P.n00 + PAIRS - 1) / PAIRS;
    int w01 = (P.n01 + PAIRS - 1) / PAIRS;
    int w11 = (P.n11 + PAIRS - 1) / PAIRS;
    P.b1 = w00; P.b2 = P.b1 + w01; P.b3 = P.b2 + w11;

    int tot = P.n00 + P.n01 + n10 + P.n11;
    if (tot) g2b_kernel<<<(tot + 255) / 256, 256>>>(P.sel00, P.n00, P.sel01, P.n01,
                                                    sel10, n10, P.sel11, P.n11, outg);
    int blocks = (P.b3 + WARPS - 1) / WARPS;
    if (blocks) fused_kernel<<<blocks, 128>>>(P);

    (void)n_in; (void)out_size; (void)E;
}